// round 1
// baseline (speedup 1.0000x reference)
#include <cuda_runtime.h>

// Channel_attention: out = gamma * softmax(Q Q^T) Q + x,  Q = x reshaped (B, N, C)
// B=2, N=8192, C=64. Flash-attention streaming kernel, fp32 SIMT.

#define BM 64          // query rows per block
#define BN 64          // key rows per iteration
#define CH 64          // channels
#define NPOS 8192
#define NTILES (NPOS / BN)
#define S1 68          // smem row stride (floats): mult of 4 (float4 align), pads banks

// smem: Qc [CH][S1] (c-major), Kc [CH][S1] (c-major), Kj [BN][S1] (j-major), Pt [BN][S1] (P^T)
#define SMEM_FLOATS (4 * CH * S1)
#define SMEM_BYTES  (SMEM_FLOATS * 4)

__global__ __launch_bounds__(256) void channel_attn_kernel(
    const float* __restrict__ x,
    const float* __restrict__ gamma_p,
    float* __restrict__ out)
{
    extern __shared__ float sm[];
    float* Qc = sm;
    float* Kc = sm + CH * S1;
    float* Kj = sm + 2 * CH * S1;
    float* Pt = sm + 3 * CH * S1;

    const int tid = threadIdx.x;
    const int tx = tid & 15;       // 16 col-groups
    const int ty = tid >> 4;       // 16 row-groups
    const int r0 = ty * 4;         // 4 rows per thread
    const int c0 = tx * 4;         // 4 cols per thread

    const int b  = blockIdx.y;
    const int i0 = blockIdx.x * BM;
    const float* xb = x + (size_t)b * NPOS * CH;

    // ---- load Q tile, transposed to c-major (conflict-free scalar STS) ----
    #pragma unroll
    for (int it = 0; it < 4; ++it) {
        int lin = it * 256 + tid;          // 0..1023
        int j   = lin & 63;                // row within tile
        int c4  = (lin >> 6) << 2;         // channel group
        float4 g = *(const float4*)(xb + (size_t)(i0 + j) * CH + c4);
        Qc[(c4 + 0) * S1 + j] = g.x;
        Qc[(c4 + 1) * S1 + j] = g.y;
        Qc[(c4 + 2) * S1 + j] = g.z;
        Qc[(c4 + 3) * S1 + j] = g.w;
    }

    float m_i[4], l_i[4], O[4][4];
    #pragma unroll
    for (int ri = 0; ri < 4; ++ri) {
        m_i[ri] = -1e30f;
        l_i[ri] = 0.0f;
        #pragma unroll
        for (int ci = 0; ci < 4; ++ci) O[ri][ci] = 0.0f;
    }

    for (int jt = 0; jt < NTILES; ++jt) {
        __syncthreads();   // prior iter's smem reads complete before K overwrite

        // ---- load K/V tile: both c-major (Kc) and j-major (Kj) ----
        const float* kb = xb + (size_t)jt * BN * CH;
        #pragma unroll
        for (int it = 0; it < 4; ++it) {
            int lin = it * 256 + tid;
            int j   = lin & 63;
            int c4  = (lin >> 6) << 2;
            float4 g = *(const float4*)(kb + (size_t)j * CH + c4);
            Kc[(c4 + 0) * S1 + j] = g.x;
            Kc[(c4 + 1) * S1 + j] = g.y;
            Kc[(c4 + 2) * S1 + j] = g.z;
            Kc[(c4 + 3) * S1 + j] = g.w;
            *(float4*)(Kj + j * S1 + c4) = g;
        }
        __syncthreads();

        // ---- GEMM1: S = Q_tile @ K_tile^T (outer product over channels) ----
        float S[4][4];
        #pragma unroll
        for (int ri = 0; ri < 4; ++ri)
            #pragma unroll
            for (int ci = 0; ci < 4; ++ci) S[ri][ci] = 0.0f;

        #pragma unroll 8
        for (int k = 0; k < CH; ++k) {
            float4 a  = *(const float4*)(Qc + k * S1 + r0);
            float4 bb = *(const float4*)(Kc + k * S1 + c0);
            S[0][0] = fmaf(a.x, bb.x, S[0][0]);
            S[0][1] = fmaf(a.x, bb.y, S[0][1]);
            S[0][2] = fmaf(a.x, bb.z, S[0][2]);
            S[0][3] = fmaf(a.x, bb.w, S[0][3]);
            S[1][0] = fmaf(a.y, bb.x, S[1][0]);
            S[1][1] = fmaf(a.y, bb.y, S[1][1]);
            S[1][2] = fmaf(a.y, bb.z, S[1][2]);
            S[1][3] = fmaf(a.y, bb.w, S[1][3]);
            S[2][0] = fmaf(a.z, bb.x, S[2][0]);
            S[2][1] = fmaf(a.z, bb.y, S[2][1]);
            S[2][2] = fmaf(a.z, bb.z, S[2][2]);
            S[2][3] = fmaf(a.z, bb.w, S[2][3]);
            S[3][0] = fmaf(a.w, bb.x, S[3][0]);
            S[3][1] = fmaf(a.w, bb.y, S[3][1]);
            S[3][2] = fmaf(a.w, bb.z, S[3][2]);
            S[3][3] = fmaf(a.w, bb.w, S[3][3]);
        }

        // ---- online softmax (row stats replicated across the 16 lanes of a row group) ----
        #pragma unroll
        for (int ri = 0; ri < 4; ++ri) {
            float tmax = fmaxf(fmaxf(S[ri][0], S[ri][1]), fmaxf(S[ri][2], S[ri][3]));
            #pragma unroll
            for (int off = 8; off >= 1; off >>= 1)
                tmax = fmaxf(tmax, __shfl_xor_sync(0xffffffffu, tmax, off, 16));
            float newm  = fmaxf(m_i[ri], tmax);
            float scale = __expf(m_i[ri] - newm);
            float rs = 0.0f;
            #pragma unroll
            for (int ci = 0; ci < 4; ++ci) {
                S[ri][ci] = __expf(S[ri][ci] - newm);
                rs += S[ri][ci];
            }
            #pragma unroll
            for (int off = 8; off >= 1; off >>= 1)
                rs += __shfl_xor_sync(0xffffffffu, rs, off, 16);
            l_i[ri] = l_i[ri] * scale + rs;
            m_i[ri] = newm;
            #pragma unroll
            for (int ci = 0; ci < 4; ++ci) O[ri][ci] *= scale;
        }

        // ---- stage P^T to smem for GEMM2 ----
        #pragma unroll
        for (int ri = 0; ri < 4; ++ri)
            #pragma unroll
            for (int ji = 0; ji < 4; ++ji)
                Pt[(c0 + ji) * S1 + (r0 + ri)] = S[ri][ji];
        __syncthreads();

        // ---- GEMM2: O += P @ V_tile (outer product over j) ----
        #pragma unroll 8
        for (int j = 0; j < BN; ++j) {
            float4 a  = *(const float4*)(Pt + j * S1 + r0);
            float4 bb = *(const float4*)(Kj + j * S1 + c0);
            O[0][0] = fmaf(a.x, bb.x, O[0][0]);
            O[0][1] = fmaf(a.x, bb.y, O[0][1]);
            O[0][2] = fmaf(a.x, bb.z, O[0][2]);
            O[0][3] = fmaf(a.x, bb.w, O[0][3]);
            O[1][0] = fmaf(a.y, bb.x, O[1][0]);
            O[1][1] = fmaf(a.y, bb.y, O[1][1]);
            O[1][2] = fmaf(a.y, bb.z, O[1][2]);
            O[1][3] = fmaf(a.y, bb.w, O[1][3]);
            O[2][0] = fmaf(a.z, bb.x, O[2][0]);
            O[2][1] = fmaf(a.z, bb.y, O[2][1]);
            O[2][2] = fmaf(a.z, bb.z, O[2][2]);
            O[2][3] = fmaf(a.z, bb.w, O[2][3]);
            O[3][0] = fmaf(a.w, bb.x, O[3][0]);
            O[3][1] = fmaf(a.w, bb.y, O[3][1]);
            O[3][2] = fmaf(a.w, bb.z, O[3][2]);
            O[3][3] = fmaf(a.w, bb.w, O[3][3]);
        }
    }

    // ---- epilogue: out = gamma * (O / l) + x ----
    const float g = *gamma_p;
    float* ob = out + (size_t)b * NPOS * CH;
    #pragma unroll
    for (int ri = 0; ri < 4; ++ri) {
        float inv = 1.0f / l_i[ri];
        size_t base = (size_t)(i0 + r0 + ri) * CH + c0;
        float4 xin = *(const float4*)(xb + base);
        float4 o;
        o.x = fmaf(g, O[ri][0] * inv, xin.x);
        o.y = fmaf(g, O[ri][1] * inv, xin.y);
        o.z = fmaf(g, O[ri][2] * inv, xin.z);
        o.w = fmaf(g, O[ri][3] * inv, xin.w);
        *(float4*)(ob + base) = o;
    }
}

extern "C" void kernel_launch(void* const* d_in, const int* in_sizes, int n_in,
                              void* d_out, int out_size)
{
    const float* x     = (const float*)d_in[0];
    const float* gamma = (const float*)d_in[1];
    float* out         = (float*)d_out;

    cudaFuncSetAttribute(channel_attn_kernel,
                         cudaFuncAttributeMaxDynamicSharedMemorySize, SMEM_BYTES);

    dim3 grid(NPOS / BM, 2);   // 128 row-tiles x 2 batches = 256 blocks (single wave)
    channel_attn_kernel<<<grid, 256, SMEM_BYTES>>>(x, gamma, out);
}

// round 3
// speedup vs baseline: 3.8576x; 3.8576x over previous
#include <cuda_runtime.h>
#include <cuda_fp16.h>
#include <cstdint>

#define NPOS 8192
#define CH 64
#define BM 128
#define BN 128
#define NT (NPOS / BN)
#define LOG2E 1.4426950408889634f

// ---------------- device scratch ----------------
#define TOT_ELEMS (2 * NPOS * CH)
__device__ __half g_hi[TOT_ELEMS];    // [b][n][c] fp16 hi
__device__ __half g_lo[TOT_ELEMS];    // [b][n][c] fp16 lo residual
__device__ __half g_thi[TOT_ELEMS];   // [b][c][n] transposed hi
__device__ __half g_tlo[TOT_ELEMS];   // [b][c][n] transposed lo

// ---------------- helpers ----------------
__device__ __forceinline__ uint32_t smem_u32(const void* p) {
    uint32_t a;
    asm("{ .reg .u64 t; cvta.to.shared.u64 t, %1; cvt.u32.u64 %0, t; }" : "=r"(a) : "l"(p));
    return a;
}
__device__ __forceinline__ float ex2f(float v) {
    float r; asm("ex2.approx.ftz.f32 %0, %1;" : "=f"(r) : "f"(v)); return r;
}
__device__ __forceinline__ uint32_t h2u(__half2 h) { return *reinterpret_cast<uint32_t*>(&h); }

__device__ __forceinline__ void cp_async16(uint32_t dst, const void* src) {
    asm volatile("cp.async.cg.shared.global [%0], [%1], 16;" :: "r"(dst), "l"(src) : "memory");
}
__device__ __forceinline__ void cp_commit() {
    asm volatile("cp.async.commit_group;" ::: "memory");
}
template <int N>
__device__ __forceinline__ void cp_wait() {
    asm volatile("cp.async.wait_group %0;" :: "n"(N) : "memory");
}
__device__ __forceinline__ uint32_t lds32(uint32_t addr) {
    uint32_t v; asm volatile("ld.shared.b32 %0, [%1];" : "=r"(v) : "r"(addr)); return v;
}

// mma.sync m16n8k16 f16 -> f32 accumulate (portable PTX, maps to HMMA)
__device__ __forceinline__ void mma16816(float* d, const uint32_t* a, const uint32_t* b) {
    asm volatile(
        "mma.sync.aligned.m16n8k16.row.col.f32.f16.f16.f32 "
        "{%0,%1,%2,%3}, {%4,%5,%6,%7}, {%8,%9}, {%0,%1,%2,%3};"
        : "+f"(d[0]), "+f"(d[1]), "+f"(d[2]), "+f"(d[3])
        : "r"(a[0]), "r"(a[1]), "r"(a[2]), "r"(a[3]), "r"(b[0]), "r"(b[1]));
}

// ---------------- smem layout (bytes) ----------------
#define KSTR 72     // K tile row stride in halfs (64 data + 8 pad)
#define VSTR 136    // Vt tile row stride in halfs (128 data + 8 pad)
#define OFF_KHI 0
#define OFF_KLO (128 * KSTR * 2)                 // 18432
#define OFF_VHI (OFF_KLO + 128 * KSTR * 2)       // 36864
#define OFF_VLO (OFF_VHI + 64 * VSTR * 2)        // 54272
#define BUFSZ   (OFF_VLO + 64 * VSTR * 2)        // 71680
#define SMEM_TOTAL (2 * BUFSZ)                   // 143360

// ---------------- pre-pass: fp32 -> fp16 hi/lo (+ transposed) ----------------
__global__ __launch_bounds__(256) void convert_kernel(const float* __restrict__ x)
{
    __shared__ float t[64][65];
    const int b  = blockIdx.y;
    const int n0 = blockIdx.x * 64;
    const int tid = threadIdx.x;

    const float* xb = x + ((size_t)b * NPOS + n0) * CH;
    __half* ghi = g_hi + ((size_t)b * NPOS + n0) * CH;
    __half* glo = g_lo + ((size_t)b * NPOS + n0) * CH;

    #pragma unroll
    for (int it = 0; it < 4; ++it) {
        int lin = it * 256 + tid;
        int n   = lin >> 4;
        int c4  = (lin & 15) * 4;
        float4 v = *(const float4*)(xb + (size_t)n * CH + c4);
        t[n][c4 + 0] = v.x; t[n][c4 + 1] = v.y; t[n][c4 + 2] = v.z; t[n][c4 + 3] = v.w;
        __half h0 = __float2half_rn(v.x), h1 = __float2half_rn(v.y);
        __half h2 = __float2half_rn(v.z), h3 = __float2half_rn(v.w);
        uint2 hw = make_uint2(h2u(__halves2half2(h0, h1)), h2u(__halves2half2(h2, h3)));
        *(uint2*)(ghi + (size_t)n * CH + c4) = hw;
        __half l0 = __float2half_rn(v.x - __half2float(h0));
        __half l1 = __float2half_rn(v.y - __half2float(h1));
        __half l2 = __float2half_rn(v.z - __half2float(h2));
        __half l3 = __float2half_rn(v.w - __half2float(h3));
        uint2 lw = make_uint2(h2u(__halves2half2(l0, l1)), h2u(__halves2half2(l2, l3)));
        *(uint2*)(glo + (size_t)n * CH + c4) = lw;
    }
    __syncthreads();

    __half* gth = g_thi + (size_t)b * CH * NPOS + n0;
    __half* gtl = g_tlo + (size_t)b * CH * NPOS + n0;
    #pragma unroll
    for (int it = 0; it < 2; ++it) {
        int lin = it * 256 + tid;
        int c  = lin >> 3;
        int n8 = (lin & 7) * 8;
        float f[8];
        #pragma unroll
        for (int e = 0; e < 8; ++e) f[e] = t[n8 + e][c];
        __half hh[8];
        #pragma unroll
        for (int e = 0; e < 8; ++e) hh[e] = __float2half_rn(f[e]);
        uint4 w;
        w.x = h2u(__halves2half2(hh[0], hh[1])); w.y = h2u(__halves2half2(hh[2], hh[3]));
        w.z = h2u(__halves2half2(hh[4], hh[5])); w.w = h2u(__halves2half2(hh[6], hh[7]));
        *(uint4*)(gth + (size_t)c * NPOS + n8) = w;
        __half ll[8];
        #pragma unroll
        for (int e = 0; e < 8; ++e) ll[e] = __float2half_rn(f[e] - __half2float(hh[e]));
        uint4 wl;
        wl.x = h2u(__halves2half2(ll[0], ll[1])); wl.y = h2u(__halves2half2(ll[2], ll[3]));
        wl.z = h2u(__halves2half2(ll[4], ll[5])); wl.w = h2u(__halves2half2(ll[6], ll[7]));
        *(uint4*)(gtl + (size_t)c * NPOS + n8) = wl;
    }
}

// ---------------- main flash-attention kernel (warp-mma) ----------------
__global__ __launch_bounds__(256, 1) void attn_kernel(
    const float* __restrict__ x,
    const float* __restrict__ gamma_p,
    float* __restrict__ out)
{
    extern __shared__ __align__(128) char smem[];
    const uint32_t sb = smem_u32(smem);
    const int tid  = threadIdx.x;
    const int w    = tid >> 5;
    const int lane = tid & 31;
    const int q4   = lane >> 2;    // t/4
    const int qm   = lane & 3;     // t%4
    const int b    = blockIdx.y;
    const int i0   = blockIdx.x * BM;

    const __half* xhi = g_hi  + (size_t)b * NPOS * CH;
    const __half* xlo = g_lo  + (size_t)b * NPOS * CH;
    const __half* thi = g_thi + (size_t)b * CH * NPOS;
    const __half* tlo = g_tlo + (size_t)b * CH * NPOS;

    // ---- prefetch one KV tile into buffer `buf` ----
    auto prefetch = [&](int jt, int buf) {
        const uint32_t d  = sb + (uint32_t)buf * BUFSZ;
        const int j0 = jt * BN;
        #pragma unroll
        for (int it = 0; it < 4; ++it) {           // K: 128 rows x 8 chunks
            int lin = it * 256 + tid;
            int row = lin >> 3, c16 = (lin & 7) * 8;
            uint32_t so = (uint32_t)(row * KSTR + c16) * 2;
            const size_t go = (size_t)(j0 + row) * CH + c16;
            cp_async16(d + OFF_KHI + so, xhi + go);
            cp_async16(d + OFF_KLO + so, xlo + go);
        }
        #pragma unroll
        for (int it = 0; it < 4; ++it) {           // Vt: 64 rows x 16 chunks
            int lin = it * 256 + tid;
            int row = lin >> 4, c16 = (lin & 15) * 8;
            uint32_t so = (uint32_t)(row * VSTR + c16) * 2;
            const size_t go = (size_t)row * NPOS + j0 + c16;
            cp_async16(d + OFF_VHI + so, thi + go);
            cp_async16(d + OFF_VLO + so, tlo + go);
        }
        cp_commit();
    };

    // ---- Q fragments (hi+lo), loaded once from gmem ----
    // A-frag regs order: {(r0,c), (r0+8,c), (r0,c+8), (r0+8,c+8)}
    uint32_t Qh[4][4], Ql[4][4];
    {
        const int r0 = i0 + w * 16 + q4;
        #pragma unroll
        for (int kc = 0; kc < 4; ++kc) {
            int c = kc * 16 + qm * 2;
            Qh[kc][0] = *(const uint32_t*)(xhi + (size_t)r0 * CH + c);
            Qh[kc][1] = *(const uint32_t*)(xhi + (size_t)(r0 + 8) * CH + c);
            Qh[kc][2] = *(const uint32_t*)(xhi + (size_t)r0 * CH + c + 8);
            Qh[kc][3] = *(const uint32_t*)(xhi + (size_t)(r0 + 8) * CH + c + 8);
            Ql[kc][0] = *(const uint32_t*)(xlo + (size_t)r0 * CH + c);
            Ql[kc][1] = *(const uint32_t*)(xlo + (size_t)(r0 + 8) * CH + c);
            Ql[kc][2] = *(const uint32_t*)(xlo + (size_t)r0 * CH + c + 8);
            Ql[kc][3] = *(const uint32_t*)(xlo + (size_t)(r0 + 8) * CH + c + 8);
        }
    }

    prefetch(0, 0);

    float m0 = -1e30f, m1 = -1e30f, l0 = 0.0f, l1 = 0.0f;
    float O[8][4];
    #pragma unroll
    for (int nb = 0; nb < 8; ++nb)
        #pragma unroll
        for (int e = 0; e < 4; ++e) O[nb][e] = 0.0f;

    for (int jt = 0; jt < NT; ++jt) {
        if (jt + 1 < NT) { prefetch(jt + 1, (jt + 1) & 1); cp_wait<1>(); }
        else             { cp_wait<0>(); }
        __syncthreads();

        const uint32_t kb = sb + (uint32_t)(jt & 1) * BUFSZ;

        // ---- GEMM1: S(16x128) = Qhi*Khi + Qlo*Khi + Qhi*Klo ----
        float S[16][4];
        #pragma unroll
        for (int nb = 0; nb < 16; ++nb)
            #pragma unroll
            for (int e = 0; e < 4; ++e) S[nb][e] = 0.0f;

        #pragma unroll
        for (int kc = 0; kc < 4; ++kc) {
            #pragma unroll
            for (int nb = 0; nb < 16; ++nb) {
                uint32_t ao = kb + (uint32_t)(((nb * 8 + q4) * KSTR + kc * 16 + qm * 2) * 2);
                uint32_t bh[2], bl[2];
                bh[0] = lds32(ao + OFF_KHI);  bh[1] = lds32(ao + OFF_KHI + 16);
                bl[0] = lds32(ao + OFF_KLO);  bl[1] = lds32(ao + OFF_KLO + 16);
                mma16816(S[nb], Qh[kc], bh);
                mma16816(S[nb], Ql[kc], bh);
                mma16816(S[nb], Qh[kc], bl);
            }
        }

        // ---- online softmax (rows r0 = q4, r1 = q4+8 of this warp's 16) ----
        float mx0 = -1e30f, mx1 = -1e30f;
        #pragma unroll
        for (int nb = 0; nb < 16; ++nb) {
            mx0 = fmaxf(mx0, fmaxf(S[nb][0], S[nb][1]));
            mx1 = fmaxf(mx1, fmaxf(S[nb][2], S[nb][3]));
        }
        mx0 = fmaxf(mx0, __shfl_xor_sync(0xffffffffu, mx0, 1));
        mx0 = fmaxf(mx0, __shfl_xor_sync(0xffffffffu, mx0, 2));
        mx1 = fmaxf(mx1, __shfl_xor_sync(0xffffffffu, mx1, 1));
        mx1 = fmaxf(mx1, __shfl_xor_sync(0xffffffffu, mx1, 2));
        float mn0 = fmaxf(m0, mx0), mn1 = fmaxf(m1, mx1);
        float c0 = ex2f((m0 - mn0) * LOG2E), c1 = ex2f((m1 - mn1) * LOG2E);
        m0 = mn0; m1 = mn1;

        float s0 = 0.0f, s1 = 0.0f;
        uint32_t Ph[8][4], Pl[8][4];
        #pragma unroll
        for (int kk = 0; kk < 8; ++kk) {
            #pragma unroll
            for (int t = 0; t < 2; ++t) {
                int nb = 2 * kk + t;
                float e0 = ex2f((S[nb][0] - mn0) * LOG2E);
                float e1 = ex2f((S[nb][1] - mn0) * LOG2E);
                float e2 = ex2f((S[nb][2] - mn1) * LOG2E);
                float e3 = ex2f((S[nb][3] - mn1) * LOG2E);
                s0 += e0 + e1; s1 += e2 + e3;
                __half2 h01 = __floats2half2_rn(e0, e1);
                __half2 h23 = __floats2half2_rn(e2, e3);
                Ph[kk][2 * t + 0] = h2u(h01);
                Ph[kk][2 * t + 1] = h2u(h23);
                float2 f01 = __half22float2(h01), f23 = __half22float2(h23);
                Pl[kk][2 * t + 0] = h2u(__floats2half2_rn(e0 - f01.x, e1 - f01.y));
                Pl[kk][2 * t + 1] = h2u(__floats2half2_rn(e2 - f23.x, e3 - f23.y));
            }
        }
        s0 += __shfl_xor_sync(0xffffffffu, s0, 1);
        s0 += __shfl_xor_sync(0xffffffffu, s0, 2);
        s1 += __shfl_xor_sync(0xffffffffu, s1, 1);
        s1 += __shfl_xor_sync(0xffffffffu, s1, 2);
        l0 = l0 * c0 + s0;
        l1 = l1 * c1 + s1;

        #pragma unroll
        for (int nb = 0; nb < 8; ++nb) {
            O[nb][0] *= c0; O[nb][1] *= c0; O[nb][2] *= c1; O[nb][3] *= c1;
        }

        // ---- GEMM2: O(16x64) += Phi*Vhi + Plo*Vhi + Phi*Vlo ----
        #pragma unroll
        for (int kk = 0; kk < 8; ++kk) {
            #pragma unroll
            for (int nb = 0; nb < 8; ++nb) {
                uint32_t ao = kb + (uint32_t)(((nb * 8 + q4) * VSTR + kk * 16 + qm * 2) * 2);
                uint32_t bh[2], bl[2];
                bh[0] = lds32(ao + OFF_VHI);  bh[1] = lds32(ao + OFF_VHI + 16);
                bl[0] = lds32(ao + OFF_VLO);  bl[1] = lds32(ao + OFF_VLO + 16);
                mma16816(O[nb], Ph[kk], bh);
                mma16816(O[nb], Pl[kk], bh);
                mma16816(O[nb], Ph[kk], bl);
            }
        }
        __syncthreads();
    }

    // ---- epilogue: out = gamma * (O / l) + x ----
    const float inv0 = 1.0f / l0, inv1 = 1.0f / l1;
    const float gm = __ldg(gamma_p);
    const float* xb = x   + (size_t)b * NPOS * CH;
    float*       ob = out + (size_t)b * NPOS * CH;
    const int gr0 = i0 + w * 16 + q4;
    const int gr1 = gr0 + 8;
    #pragma unroll
    for (int nb = 0; nb < 8; ++nb) {
        int c = nb * 8 + qm * 2;
        float2 xv0 = *(const float2*)(xb + (size_t)gr0 * CH + c);
        float2 xv1 = *(const float2*)(xb + (size_t)gr1 * CH + c);
        float2 o0, o1;
        o0.x = fmaf(gm, O[nb][0] * inv0, xv0.x);
        o0.y = fmaf(gm, O[nb][1] * inv0, xv0.y);
        o1.x = fmaf(gm, O[nb][2] * inv1, xv1.x);
        o1.y = fmaf(gm, O[nb][3] * inv1, xv1.y);
        *(float2*)(ob + (size_t)gr0 * CH + c) = o0;
        *(float2*)(ob + (size_t)gr1 * CH + c) = o1;
    }
}

// ---------------- launch ----------------
extern "C" void kernel_launch(void* const* d_in, const int* in_sizes, int n_in,
                              void* d_out, int out_size)
{
    const float* x     = (const float*)d_in[0];
    const float* gamma = (const float*)d_in[1];
    float* out         = (float*)d_out;

    cudaFuncSetAttribute(attn_kernel,
                         cudaFuncAttributeMaxDynamicSharedMemorySize, SMEM_TOTAL);

    convert_kernel<<<dim3(NPOS / 64, 2), 256>>>(x);
    attn_kernel<<<dim3(NPOS / BM, 2), 256, SMEM_TOTAL>>>(x, gamma, out);
}